// round 2
// baseline (speedup 1.0000x reference)
#include <cuda_runtime.h>
#include <cstdint>

// Problem constants (fixed by the reference setup_inputs)
#define BATCH 4
#define NNODES 10000
#define NEDGES 160000
#define HDIM 128
#define FDIM 32
#define KDIM 288          // F + 2H
#define MDIM 256          // output features
#define OUT_ELEMS (BATCH * NNODES * MDIM)   // 10,240,000 floats

// Tiling
#define BM 128            // edges per block
#define BN 128            // output features per block
#define BK 32             // k-slice (aligns concat boundaries: F=32, H=128=4*32)
#define NTHREADS 256      // 16 x 16 thread grid, 8x8 per-thread tile

__global__ void zero_out_kernel(float4* __restrict__ out, int n4) {
    int i = blockIdx.x * blockDim.x + threadIdx.x;
    int stride = gridDim.x * blockDim.x;
    float4 z = make_float4(0.f, 0.f, 0.f, 0.f);
    for (; i < n4; i += stride) out[i] = z;
}

__global__ __launch_bounds__(NTHREADS, 2)
void msg_gemm_kernel(const float* __restrict__ hidden,        // [B, N, H]
                     const float* __restrict__ edge_feat,     // [B, E, F]
                     const int* __restrict__ esrc,            // [B, E] (int32 — JAX canonicalizes int64->int32)
                     const int* __restrict__ etgt,            // [B, E]
                     const float* __restrict__ W,             // [K, M] row-major
                     const float* __restrict__ bias,          // [M]
                     float* __restrict__ out)                 // [B, N, M]
{
    __shared__ float As[BM][BK + 1];   // pad 33: conflict-free fill + column reads
    __shared__ float Bs[BK][BN];
    __shared__ int   sSrc[BM];
    __shared__ int   sTgt[BM];

    const int b  = blockIdx.z;
    const int e0 = blockIdx.x * BM;
    const int n0 = blockIdx.y * BN;
    const int tid = threadIdx.x;
    const int tx = tid & 15;           // output-feature direction (8 each)
    const int ty = tid >> 4;           // edge direction (8 each)

    // Load the 128 edge indices for this tile
    if (tid < BM) {
        sSrc[tid] = esrc[(size_t)b * NEDGES + e0 + tid];
        sTgt[tid] = etgt[(size_t)b * NEDGES + e0 + tid];
    }
    __syncthreads();

    float acc[8][8];
    #pragma unroll
    for (int i = 0; i < 8; ++i)
        #pragma unroll
        for (int j = 0; j < 8; ++j) acc[i][j] = 0.f;

    // K loop: 9 tiles of 32. Tile 0 = edge_features, 1..4 = hidden[src], 5..8 = hidden[tgt].
    for (int t = 0; t < 9; ++t) {
        // ---- fill As: 128 rows x 32 cols, 4 float4 per thread ----
        #pragma unroll
        for (int i = 0; i < 4; ++i) {
            int idx = tid + i * NTHREADS;       // 0..1023
            int r   = idx >> 3;                 // edge row 0..127
            int c4  = (idx & 7) << 2;           // col 0,4,...,28
            const float* src;
            if (t == 0) {
                src = edge_feat + ((size_t)b * NEDGES + e0 + r) * FDIM + c4;
            } else if (t < 5) {
                src = hidden + ((size_t)b * NNODES + sSrc[r]) * HDIM + (t - 1) * 32 + c4;
            } else {
                src = hidden + ((size_t)b * NNODES + sTgt[r]) * HDIM + (t - 5) * 32 + c4;
            }
            float4 v = *(const float4*)src;
            As[r][c4 + 0] = v.x;
            As[r][c4 + 1] = v.y;
            As[r][c4 + 2] = v.z;
            As[r][c4 + 3] = v.w;
        }
        // ---- fill Bs: 32 rows x 128 cols of W, 4 float4 per thread ----
        #pragma unroll
        for (int i = 0; i < 4; ++i) {
            int idx = tid + i * NTHREADS;       // 0..1023
            int kr  = idx >> 5;                 // k row 0..31
            int c4  = (idx & 31) << 2;          // col 0,4,...,124
            float4 v = *(const float4*)(W + (size_t)(t * BK + kr) * MDIM + n0 + c4);
            *(float4*)&Bs[kr][c4] = v;
        }
        __syncthreads();

        // ---- 128x128x32 FFMA ----
        #pragma unroll
        for (int kk = 0; kk < BK; ++kk) {
            float a[8];
            #pragma unroll
            for (int i = 0; i < 8; ++i) a[i] = As[ty * 8 + i][kk];
            float4 b0 = *(const float4*)&Bs[kk][tx * 8];
            float4 b1 = *(const float4*)&Bs[kk][tx * 8 + 4];
            float bb[8] = {b0.x, b0.y, b0.z, b0.w, b1.x, b1.y, b1.z, b1.w};
            #pragma unroll
            for (int i = 0; i < 8; ++i)
                #pragma unroll
                for (int j = 0; j < 8; ++j)
                    acc[i][j] = fmaf(a[i], bb[j], acc[i][j]);
        }
        __syncthreads();
    }

    // ---- epilogue: bias + ReLU + vectorized scatter-add over edge_targets ----
    float4 bv0 = *(const float4*)(bias + n0 + tx * 8);
    float4 bv1 = *(const float4*)(bias + n0 + tx * 8 + 4);

    #pragma unroll
    for (int i = 0; i < 8; ++i) {
        int r    = ty * 8 + i;
        int node = sTgt[r];
        float* dst = out + ((size_t)b * NNODES + node) * MDIM + n0 + tx * 8;
        float v0 = fmaxf(acc[i][0] + bv0.x, 0.f);
        float v1 = fmaxf(acc[i][1] + bv0.y, 0.f);
        float v2 = fmaxf(acc[i][2] + bv0.z, 0.f);
        float v3 = fmaxf(acc[i][3] + bv0.w, 0.f);
        float v4 = fmaxf(acc[i][4] + bv1.x, 0.f);
        float v5 = fmaxf(acc[i][5] + bv1.y, 0.f);
        float v6 = fmaxf(acc[i][6] + bv1.z, 0.f);
        float v7 = fmaxf(acc[i][7] + bv1.w, 0.f);
        asm volatile("red.global.add.v4.f32 [%0], {%1,%2,%3,%4};"
                     :: "l"(dst), "f"(v0), "f"(v1), "f"(v2), "f"(v3) : "memory");
        asm volatile("red.global.add.v4.f32 [%0], {%1,%2,%3,%4};"
                     :: "l"(dst + 4), "f"(v4), "f"(v5), "f"(v6), "f"(v7) : "memory");
    }
}

extern "C" void kernel_launch(void* const* d_in, const int* in_sizes, int n_in,
                              void* d_out, int out_size) {
    const float* hidden    = (const float*)d_in[0];  // [4,10000,128]
    const float* edge_feat = (const float*)d_in[1];  // [4,160000,32]
    const int*   esrc      = (const int*)d_in[2];    // [4,160000] int32
    const int*   etgt      = (const int*)d_in[3];    // [4,160000] int32
    const float* W         = (const float*)d_in[4];  // [288,256]
    const float* bias      = (const float*)d_in[5];  // [256]
    float* out = (float*)d_out;

    // d_out is poisoned; zero it (we scatter-add into it).
    zero_out_kernel<<<2560, 256>>>((float4*)out, OUT_ELEMS / 4);

    dim3 grid(NEDGES / BM, MDIM / BN, BATCH);   // 1250 x 2 x 4 = 10000 CTAs
    msg_gemm_kernel<<<grid, NTHREADS>>>(hidden, edge_feat, esrc, etgt, W, bias, out);
}

// round 7
// speedup vs baseline: 2.6625x; 2.6625x over previous
#include <cuda_runtime.h>
#include <cstdint>

// Problem constants
#define BATCH 4
#define NNODES 10000
#define NEDGES 160000
#define HDIM 128
#define FDIM 32
#define KDIM 288
#define MDIM 256
#define OUT_ELEMS (BATCH * NNODES * MDIM)

// Tiling: CTA = 128 edges x 128 outputs, K chunked by 32. 8 warps = 4(m) x 2(n).
#define BM 128
#define BN 128
#define BK 32
#define NCHUNKS 9
#define NTHREADS 256

// Row pads chosen so fragment loads are bank-conflict-free:
// As word index = 36*r + col -> bank (4r+col)&31 ; lanes (g=lane/4, c=lane&3) hit 4g+c: a permutation.
// Bs word index = 132*k + col -> bank (4k+col)&31 ; lanes hit 4c+g: a permutation.
#define APAD 36
#define BPAD 132

__device__ __forceinline__ uint32_t f32_to_tf32_rna(float v) {
    uint32_t r;
    asm("cvt.rna.tf32.f32 %0, %1;" : "=r"(r) : "f"(v));
    return r;
}

__device__ __forceinline__ void mma_tf32(float c[4], const uint32_t a[4],
                                         uint32_t b0, uint32_t b1) {
    asm volatile(
        "mma.sync.aligned.m16n8k8.row.col.f32.tf32.tf32.f32 "
        "{%0,%1,%2,%3}, {%4,%5,%6,%7}, {%8,%9}, {%0,%1,%2,%3};"
        : "+f"(c[0]), "+f"(c[1]), "+f"(c[2]), "+f"(c[3])
        : "r"(a[0]), "r"(a[1]), "r"(a[2]), "r"(a[3]), "r"(b0), "r"(b1));
}

__global__ void zero_out_kernel(float4* __restrict__ out, int n4) {
    int i = blockIdx.x * blockDim.x + threadIdx.x;
    int stride = gridDim.x * blockDim.x;
    float4 z = make_float4(0.f, 0.f, 0.f, 0.f);
    for (; i < n4; i += stride) out[i] = z;
}

__global__ __launch_bounds__(NTHREADS, 2)
void msg_mma_kernel(const float* __restrict__ hidden,        // [B, N, H]
                    const float* __restrict__ edge_feat,     // [B, E, F]
                    const int* __restrict__ esrc,            // [B, E]
                    const int* __restrict__ etgt,            // [B, E]
                    const float* __restrict__ W,             // [K, M]
                    const float* __restrict__ bias,          // [M]
                    float* __restrict__ out)                 // [B, N, M]
{
    __shared__ uint32_t As[BM][APAD];     // tf32 bit patterns, 18432 B
    __shared__ uint32_t Bs[BK][BPAD];     // 16896 B
    __shared__ int sSrc[BM];
    __shared__ int sTgt[BM];

    const int tid  = threadIdx.x;
    const int wid  = tid >> 5;
    const int lane = tid & 31;
    const int warp_m = wid & 3;           // 4 warps over 128 rows (32 each)
    const int warp_n = wid >> 2;          // 2 warps over 128 cols (64 each)
    const int g = lane >> 2;              // group id 0..7
    const int c = lane & 3;               // thread-in-group 0..3

    const int b  = blockIdx.z;
    const int e0 = blockIdx.x * BM;
    const int n0 = blockIdx.y * BN;

    if (tid < BM) {
        sSrc[tid] = esrc[(size_t)b * NEDGES + e0 + tid];
        sTgt[tid] = etgt[(size_t)b * NEDGES + e0 + tid];
    }
    __syncthreads();

    // Per-thread fill coordinates (fixed across chunks)
    const int ar = tid >> 1;              // A row 0..127       (2 threads/row)
    const int aj = (tid & 1) * 4;         // A float4 slot (x2) -> cols 0..15/16..31
    const int bkr = tid >> 3;             // B k-row 0..31      (8 threads/row)
    const int bj  = (tid & 7) * 4;        // B float4 slot      -> 32 cols... (x? see loops)

    float cacc[2][8][4];
    #pragma unroll
    for (int mt = 0; mt < 2; ++mt)
        #pragma unroll
        for (int nt = 0; nt < 8; ++nt)
            #pragma unroll
            for (int q = 0; q < 4; ++q) cacc[mt][nt][q] = 0.f;

    // Register prefetch buffers: A = 4 float4 (rows tid/8? see mapping), B = 4 float4.
    // A mapping: id = tid + i*256, r = id>>3 (row), j = id&7 (float4 slot).
    float4 prefA[4];
    float4 prefB[4];

    // ---- issue gather loads for chunk t into prefA ----
    auto issueA = [&](int t) {
        #pragma unroll
        for (int i = 0; i < 4; ++i) {
            int id = tid + i * NTHREADS;
            int r  = id >> 3;
            int j  = id & 7;
            const float* src;
            if (t == 0) {
                src = edge_feat + ((size_t)b * NEDGES + e0 + r) * FDIM + j * 4;
            } else if (t < 5) {
                src = hidden + ((size_t)b * NNODES + sSrc[r]) * HDIM + (t - 1) * 32 + j * 4;
            } else {
                src = hidden + ((size_t)b * NNODES + sTgt[r]) * HDIM + (t - 5) * 32 + j * 4;
            }
            prefA[i] = *(const float4*)src;
        }
    };
    auto issueB = [&](int t) {
        #pragma unroll
        for (int i = 0; i < 4; ++i) {
            int id = tid + i * NTHREADS;
            int kr = id >> 5;
            int j  = id & 31;
            prefB[i] = *(const float4*)(W + (size_t)(t * BK + kr) * MDIM + n0 + j * 4);
        }
    };

    issueA(0);
    issueB(0);

    for (int t = 0; t < NCHUNKS; ++t) {
        // ---- store prefetched chunk into smem (convert to tf32-rna) ----
        #pragma unroll
        for (int i = 0; i < 4; ++i) {
            int id = tid + i * NTHREADS;
            int r  = id >> 3;
            int j  = id & 7;
            uint4 u;
            u.x = f32_to_tf32_rna(prefA[i].x);
            u.y = f32_to_tf32_rna(prefA[i].y);
            u.z = f32_to_tf32_rna(prefA[i].z);
            u.w = f32_to_tf32_rna(prefA[i].w);
            *(uint4*)&As[r][j * 4] = u;
        }
        #pragma unroll
        for (int i = 0; i < 4; ++i) {
            int id = tid + i * NTHREADS;
            int kr = id >> 5;
            int j  = id & 31;
            uint4 u;
            u.x = f32_to_tf32_rna(prefB[i].x);
            u.y = f32_to_tf32_rna(prefB[i].y);
            u.z = f32_to_tf32_rna(prefB[i].z);
            u.w = f32_to_tf32_rna(prefB[i].w);
            *(uint4*)&Bs[kr][j * 4] = u;
        }
        __syncthreads();

        // ---- prefetch next chunk (LDGs overlap with the MMAs below) ----
        if (t + 1 < NCHUNKS) {
            issueA(t + 1);
            issueB(t + 1);
        }

        // ---- compute: 4 k-steps of m16n8k8 per chunk ----
        #pragma unroll
        for (int ks = 0; ks < 4; ++ks) {
            const int k0 = ks * 8;
            uint32_t a[2][4];
            #pragma unroll
            for (int mt = 0; mt < 2; ++mt) {
                int rb = warp_m * 32 + mt * 16;
                a[mt][0] = As[rb + g][k0 + c];
                a[mt][1] = As[rb + g + 8][k0 + c];
                a[mt][2] = As[rb + g][k0 + c + 4];
                a[mt][3] = As[rb + g + 8][k0 + c + 4];
            }
            #pragma unroll
            for (int nt = 0; nt < 8; ++nt) {
                int cb = warp_n * 64 + nt * 8 + g;
                uint32_t b0 = Bs[k0 + c][cb];
                uint32_t b1 = Bs[k0 + c + 4][cb];
                mma_tf32(cacc[0][nt], a[0], b0, b1);
                mma_tf32(cacc[1][nt], a[1], b0, b1);
            }
        }
        __syncthreads();
    }

    // ---- epilogue: bias + ReLU + red.v2 scatter over edge_targets ----
    #pragma unroll
    for (int nt = 0; nt < 8; ++nt) {
        const int col = n0 + warp_n * 64 + nt * 8 + c * 2;
        const float bv0 = __ldg(bias + col);
        const float bv1 = __ldg(bias + col + 1);
        #pragma unroll
        for (int mt = 0; mt < 2; ++mt) {
            const int row0 = warp_m * 32 + mt * 16 + g;
            const int node0 = sTgt[row0];
            const int node1 = sTgt[row0 + 8];
            float v0 = fmaxf(cacc[mt][nt][0] + bv0, 0.f);
            float v1 = fmaxf(cacc[mt][nt][1] + bv1, 0.f);
            float v2 = fmaxf(cacc[mt][nt][2] + bv0, 0.f);
            float v3 = fmaxf(cacc[mt][nt][3] + bv1, 0.f);
            float* d0 = out + ((size_t)b * NNODES + node0) * MDIM + col;
            float* d1 = out + ((size_t)b * NNODES + node1) * MDIM + col;
            asm volatile("red.global.add.v2.f32 [%0], {%1,%2};"
                         :: "l"(d0), "f"(v0), "f"(v1) : "memory");
            asm volatile("red.global.add.v2.f32 [%0], {%1,%2};"
                         :: "l"(d1), "f"(v2), "f"(v3) : "memory");
        }
    }
}

extern "C" void kernel_launch(void* const* d_in, const int* in_sizes, int n_in,
                              void* d_out, int out_size) {
    const float* hidden    = (const float*)d_in[0];
    const float* edge_feat = (const float*)d_in[1];
    const int*   esrc      = (const int*)d_in[2];
    const int*   etgt      = (const int*)d_in[3];
    const float* W         = (const float*)d_in[4];
    const float* bias      = (const float*)d_in[5];
    float* out = (float*)d_out;

    zero_out_kernel<<<2560, 256>>>((float4*)out, OUT_ELEMS / 4);

    dim3 grid(NEDGES / BM, MDIM / BN, BATCH);   // 1250 x 2 x 4 = 10000 CTAs
    msg_mma_kernel<<<grid, NTHREADS>>>(hidden, edge_feat, esrc, etgt, W, bias, out);
}

// round 12
// speedup vs baseline: 5.4267x; 2.0382x over previous
#include <cuda_runtime.h>
#include <cstdint>

// Problem constants
#define BATCH 4
#define NNODES 10000
#define NEDGES 160000
#define HDIM 128
#define FDIM 32
#define MDIM 256
#define NROWS (BATCH * NNODES)            // 40000 node rows
#define EFLAT (BATCH * NEDGES)            // 640000 edge rows
#define OUT_ELEMS (NROWS * MDIM)

// Shared tiling for both mma kernels
#define BM 128
#define BN 128
#define BK 32
#define NTHREADS 256
#define APAD 36
#define BPAD 132

// Node projections scratch: hs = h@W_s + bias, ht = h@W_t   (~82 MB static)
__device__ float g_hs[NROWS * MDIM];
__device__ float g_ht[NROWS * MDIM];

__device__ __forceinline__ uint32_t f32_to_tf32_rna(float v) {
    uint32_t r;
    asm("cvt.rna.tf32.f32 %0, %1;" : "=r"(r) : "f"(v));
    return r;
}

__device__ __forceinline__ void mma_tf32(float c[4], const uint32_t a[4],
                                         uint32_t b0, uint32_t b1) {
    asm volatile(
        "mma.sync.aligned.m16n8k8.row.col.f32.tf32.tf32.f32 "
        "{%0,%1,%2,%3}, {%4,%5,%6,%7}, {%8,%9}, {%0,%1,%2,%3};"
        : "+f"(c[0]), "+f"(c[1]), "+f"(c[2]), "+f"(c[3])
        : "r"(a[0]), "r"(a[1]), "r"(a[2]), "r"(a[3]), "r"(b0), "r"(b1));
}

__global__ void zero_out_kernel(float4* __restrict__ out, int n4) {
    int i = blockIdx.x * blockDim.x + threadIdx.x;
    int stride = gridDim.x * blockDim.x;
    float4 z = make_float4(0.f, 0.f, 0.f, 0.f);
    for (; i < n4; i += stride) out[i] = z;
}

// ---------------- node projection: hs = h@W[32:160] + bias, ht = h@W[160:288] ----------------
// grid: (ceil(NROWS/128), 2 col-tiles, 2 {hs,ht})
__global__ __launch_bounds__(NTHREADS, 2)
void node_proj_kernel(const float* __restrict__ hidden,   // [NROWS, 128]
                      const float* __restrict__ W,        // [288, 256]
                      const float* __restrict__ bias)     // [256]
{
    __shared__ uint32_t As[BM][APAD];
    __shared__ uint32_t Bs[BK][BPAD];

    const int tid  = threadIdx.x;
    const int wid  = tid >> 5;
    const int lane = tid & 31;
    const int warp_m = wid & 3;
    const int warp_n = wid >> 2;
    const int g = lane >> 2;
    const int c = lane & 3;

    const int r0 = blockIdx.x * BM;
    const int n0 = blockIdx.y * BN;
    const int which = blockIdx.z;          // 0 = hs (W rows 32.., +bias), 1 = ht (W rows 160..)
    const int woff = which ? 160 : 32;
    float* dst = which ? g_ht : g_hs;

    float cacc[2][8][4];
    #pragma unroll
    for (int mt = 0; mt < 2; ++mt)
        #pragma unroll
        for (int nt = 0; nt < 8; ++nt)
            #pragma unroll
            for (int q = 0; q < 4; ++q) cacc[mt][nt][q] = 0.f;

    for (int t = 0; t < 4; ++t) {          // K=128 in 4 chunks of 32
        #pragma unroll
        for (int i = 0; i < 4; ++i) {
            int id = tid + i * NTHREADS;
            int r  = id >> 3;
            int j  = id & 7;
            int row = r0 + r;
            if (row >= NROWS) row = NROWS - 1;   // clamp (grid overshoot)
            float4 v = *(const float4*)(hidden + (size_t)row * HDIM + t * 32 + j * 4);
            uint4 u;
            u.x = f32_to_tf32_rna(v.x);
            u.y = f32_to_tf32_rna(v.y);
            u.z = f32_to_tf32_rna(v.z);
            u.w = f32_to_tf32_rna(v.w);
            *(uint4*)&As[r][j * 4] = u;
        }
        #pragma unroll
        for (int i = 0; i < 4; ++i) {
            int id = tid + i * NTHREADS;
            int kr = id >> 5;
            int j  = id & 31;
            float4 v = *(const float4*)(W + (size_t)(woff + t * BK + kr) * MDIM + n0 + j * 4);
            uint4 u;
            u.x = f32_to_tf32_rna(v.x);
            u.y = f32_to_tf32_rna(v.y);
            u.z = f32_to_tf32_rna(v.z);
            u.w = f32_to_tf32_rna(v.w);
            *(uint4*)&Bs[kr][j * 4] = u;
        }
        __syncthreads();

        #pragma unroll
        for (int ks = 0; ks < 4; ++ks) {
            const int k0 = ks * 8;
            uint32_t a[2][4];
            #pragma unroll
            for (int mt = 0; mt < 2; ++mt) {
                int rb = warp_m * 32 + mt * 16;
                a[mt][0] = As[rb + g][k0 + c];
                a[mt][1] = As[rb + g + 8][k0 + c];
                a[mt][2] = As[rb + g][k0 + c + 4];
                a[mt][3] = As[rb + g + 8][k0 + c + 4];
            }
            #pragma unroll
            for (int nt = 0; nt < 8; ++nt) {
                int cb = warp_n * 64 + nt * 8 + g;
                uint32_t b0 = Bs[k0 + c][cb];
                uint32_t b1 = Bs[k0 + c + 4][cb];
                mma_tf32(cacc[0][nt], a[0], b0, b1);
                mma_tf32(cacc[1][nt], a[1], b0, b1);
            }
        }
        __syncthreads();
    }

    // store (hs gets bias folded in)
    #pragma unroll
    for (int nt = 0; nt < 8; ++nt) {
        const int col = n0 + warp_n * 64 + nt * 8 + c * 2;
        const float bv0 = which ? 0.f : __ldg(bias + col);
        const float bv1 = which ? 0.f : __ldg(bias + col + 1);
        #pragma unroll
        for (int mt = 0; mt < 2; ++mt) {
            const int rowA = r0 + warp_m * 32 + mt * 16 + g;
            const int rowB = rowA + 8;
            if (rowA < NROWS) {
                float2 v = make_float2(cacc[mt][nt][0] + bv0, cacc[mt][nt][1] + bv1);
                *(float2*)(dst + (size_t)rowA * MDIM + col) = v;
            }
            if (rowB < NROWS) {
                float2 v = make_float2(cacc[mt][nt][2] + bv0, cacc[mt][nt][3] + bv1);
                *(float2*)(dst + (size_t)rowB * MDIM + col) = v;
            }
        }
    }
}

// ---------------- edge kernel: acc = ef@W[0:32]; out += relu(acc + hs[src] + ht[tgt]) ----------------
// grid: (EFLAT/128, 2 col-tiles)
__global__ __launch_bounds__(NTHREADS, 2)
void edge_kernel(const float* __restrict__ edge_feat,     // [EFLAT, 32]
                 const int* __restrict__ esrc,            // [EFLAT]
                 const int* __restrict__ etgt,            // [EFLAT]
                 const float* __restrict__ W,             // [288, 256]
                 float* __restrict__ out)                 // [NROWS, 256]
{
    __shared__ uint32_t As[BM][APAD];
    __shared__ uint32_t Bs[BK][BPAD];
    __shared__ int sSrc[BM];   // node row with batch offset baked in
    __shared__ int sTgt[BM];

    const int tid  = threadIdx.x;
    const int wid  = tid >> 5;
    const int lane = tid & 31;
    const int warp_m = wid & 3;
    const int warp_n = wid >> 2;
    const int g = lane >> 2;
    const int c = lane & 3;

    const int etile = blockIdx.x;                 // 0..4999
    const int b = etile / (NEDGES / BM);          // 1250 tiles per batch
    const int e0 = etile * BM;                    // flat edge row base
    const int n0 = blockIdx.y * BN;

    if (tid < BM) {
        sSrc[tid] = b * NNODES + esrc[e0 + tid];
        sTgt[tid] = b * NNODES + etgt[e0 + tid];
    }

    float cacc[2][8][4];
    #pragma unroll
    for (int mt = 0; mt < 2; ++mt)
        #pragma unroll
        for (int nt = 0; nt < 8; ++nt)
            #pragma unroll
            for (int q = 0; q < 4; ++q) cacc[mt][nt][q] = 0.f;

    // single K-chunk (K=32): fill A (coalesced ef) and B (W rows 0..31)
    #pragma unroll
    for (int i = 0; i < 4; ++i) {
        int id = tid + i * NTHREADS;
        int r  = id >> 3;
        int j  = id & 7;
        float4 v = *(const float4*)(edge_feat + (size_t)(e0 + r) * FDIM + j * 4);
        uint4 u;
        u.x = f32_to_tf32_rna(v.x);
        u.y = f32_to_tf32_rna(v.y);
        u.z = f32_to_tf32_rna(v.z);
        u.w = f32_to_tf32_rna(v.w);
        *(uint4*)&As[r][j * 4] = u;
    }
    #pragma unroll
    for (int i = 0; i < 4; ++i) {
        int id = tid + i * NTHREADS;
        int kr = id >> 5;
        int j  = id & 31;
        float4 v = *(const float4*)(W + (size_t)kr * MDIM + n0 + j * 4);
        uint4 u;
        u.x = f32_to_tf32_rna(v.x);
        u.y = f32_to_tf32_rna(v.y);
        u.z = f32_to_tf32_rna(v.z);
        u.w = f32_to_tf32_rna(v.w);
        *(uint4*)&Bs[kr][j * 4] = u;
    }
    __syncthreads();

    #pragma unroll
    for (int ks = 0; ks < 4; ++ks) {
        const int k0 = ks * 8;
        uint32_t a[2][4];
        #pragma unroll
        for (int mt = 0; mt < 2; ++mt) {
            int rb = warp_m * 32 + mt * 16;
            a[mt][0] = As[rb + g][k0 + c];
            a[mt][1] = As[rb + g + 8][k0 + c];
            a[mt][2] = As[rb + g][k0 + c + 4];
            a[mt][3] = As[rb + g + 8][k0 + c + 4];
        }
        #pragma unroll
        for (int nt = 0; nt < 8; ++nt) {
            int cb = warp_n * 64 + nt * 8 + g;
            uint32_t b0 = Bs[k0 + c][cb];
            uint32_t b1 = Bs[k0 + c + 4][cb];
            mma_tf32(cacc[0][nt], a[0], b0, b1);
            mma_tf32(cacc[1][nt], a[1], b0, b1);
        }
    }

    // epilogue: gather node projections, relu, scatter-add
    #pragma unroll
    for (int nt = 0; nt < 8; ++nt) {
        const int col = n0 + warp_n * 64 + nt * 8 + c * 2;
        #pragma unroll
        for (int mt = 0; mt < 2; ++mt) {
            const int rA = warp_m * 32 + mt * 16 + g;
            const int rB = rA + 8;
            const int sA = sSrc[rA], tA = sTgt[rA];
            const int sB = sSrc[rB], tB = sTgt[rB];

            float2 hsA = *(const float2*)(g_hs + (size_t)sA * MDIM + col);
            float2 htA = *(const float2*)(g_ht + (size_t)tA * MDIM + col);
            float2 hsB = *(const float2*)(g_hs + (size_t)sB * MDIM + col);
            float2 htB = *(const float2*)(g_ht + (size_t)tB * MDIM + col);

            float v0 = fmaxf(cacc[mt][nt][0] + hsA.x + htA.x, 0.f);
            float v1 = fmaxf(cacc[mt][nt][1] + hsA.y + htA.y, 0.f);
            float v2 = fmaxf(cacc[mt][nt][2] + hsB.x + htB.x, 0.f);
            float v3 = fmaxf(cacc[mt][nt][3] + hsB.y + htB.y, 0.f);

            float* d0 = out + (size_t)tA * MDIM + col;
            float* d1 = out + (size_t)tB * MDIM + col;
            asm volatile("red.global.add.v2.f32 [%0], {%1,%2};"
                         :: "l"(d0), "f"(v0), "f"(v1) : "memory");
            asm volatile("red.global.add.v2.f32 [%0], {%1,%2};"
                         :: "l"(d1), "f"(v2), "f"(v3) : "memory");
        }
    }
}

extern "C" void kernel_launch(void* const* d_in, const int* in_sizes, int n_in,
                              void* d_out, int out_size) {
    const float* hidden    = (const float*)d_in[0];   // [4,10000,128] -> flat [40000,128]
    const float* edge_feat = (const float*)d_in[1];   // [4,160000,32] -> flat [640000,32]
    const int*   esrc      = (const int*)d_in[2];     // [4,160000] int32
    const int*   etgt      = (const int*)d_in[3];
    const float* W         = (const float*)d_in[4];   // [288,256]
    const float* bias      = (const float*)d_in[5];   // [256]
    float* out = (float*)d_out;

    zero_out_kernel<<<2560, 256>>>((float4*)out, OUT_ELEMS / 4);

    dim3 ngrid((NROWS + BM - 1) / BM, MDIM / BN, 2);   // 313 x 2 x 2
    node_proj_kernel<<<ngrid, NTHREADS>>>(hidden, W, bias);

    dim3 egrid(EFLAT / BM, MDIM / BN, 1);              // 5000 x 2
    edge_kernel<<<egrid, NTHREADS>>>(edge_feat, esrc, etgt, W, out);
}